// round 3
// baseline (speedup 1.0000x reference)
#include <cuda_runtime.h>

// GAT layer, shapes fixed: n=16, t=12, N=64, c=o=64. adj is dead code.
// Degenerate tile/cat(dim=1)/view algebra (verified R1/R2, rel_err 4e-7):
//   wa0 = W @ a[:64], wa1 = W @ a[64:]
//   p[T,u] = inp[n,T,u,:]·wa0,  q[T,u] = inp[n,T,u,:]·wa1
//   tt<6 : e[v,w] = lrelu( (p+q)[2tt+(v>=32), (2v+(w>=32))%64] )  -> 2 distinct
//          values per softmax row -> closed-form softmax.
//   tt>=6: e[v,w] = lrelu( p[2(tt-6)+(v>=32),(2w)%64] + q[...,(2w+1)%64] )
//          -> 2 distinct attention rows.
//   h_prime = (attn @ inp[n,tt]) @ W; elu.
// R3: single front-loaded DRAM round trip (W,T0,T1,C all at once, MLP=16),
// padded stride-65 row-major tiles (conflict-free in every stage), fused
// e+softmax, colsums overlapped with wa. 4-5 syncs total.

#define NT 12
#define LRELU_A 0.2f
#define TS 65

struct Smem {
    float Ws[64 * TS];   // Ws[c*TS+o] = W[c][o]
    float X0[64 * TS];   // X0[u*TS+c] = inp[T0][u][c]
    float X1[64 * TS];
    float XC[64 * TS];   // current time slice tt
    float a_s[128];
    float wa0[64], wa1[64];
    float p0[64], q0[64], p1[64], q1[64];
    float s0[64], s1[64];
    float v0[64], v1[64];
    float h0[64], h1[64];
};

__device__ __forceinline__ float wsum(float v) {
#pragma unroll
    for (int s = 16; s; s >>= 1) v += __shfl_xor_sync(0xffffffffu, v, s);
    return v;
}
__device__ __forceinline__ float wmax(float v) {
#pragma unroll
    for (int s = 16; s; s >>= 1) v = fmaxf(v, __shfl_xor_sync(0xffffffffu, v, s));
    return v;
}
__device__ __forceinline__ float elu1(float x) { return x > 0.0f ? x : expm1f(x); }
__device__ __forceinline__ float lrelu(float x) { return x > 0.0f ? x : LRELU_A * x; }

__device__ __forceinline__ void st4(float* base, float4 v) {
    base[0] = v.x; base[1] = v.y; base[2] = v.z; base[3] = v.w;
}

__global__ void __launch_bounds__(256) gat_kernel(
    const float* __restrict__ inp, const float* __restrict__ W,
    const float* __restrict__ a, float* __restrict__ out_h,
    float* __restrict__ out_att)
{
    extern __shared__ Smem sm[];
    Smem& S = sm[0];

    const int b    = blockIdx.x;          // nn*12 + tt
    const int tt   = b % NT;
    const int nn   = b / NT;
    const int tid  = threadIdx.x;
    const int lane = tid & 31;
    const int warp = tid >> 5;

    const bool first = (tt < 6);
    const int  T0    = first ? 2 * tt : 2 * (tt - 6);
    const float* __restrict__ iT0 = inp + ((size_t)nn * NT + T0) * 4096;
    const float* __restrict__ iT1 = iT0 + 4096;
    const float* __restrict__ iC  = inp + ((size_t)nn * NT + tt) * 4096;

    // ---- stage 0: issue ALL global loads up front (MLP = 16 LDG.128) ------
    float4 rW[4], r0[4], r1[4], rC[4];
#pragma unroll
    for (int i = 0; i < 4; ++i) {
        int idx = tid * 4 + i * 1024;
        rW[i] = *reinterpret_cast<const float4*>(W   + idx);
        r0[i] = *reinterpret_cast<const float4*>(iT0 + idx);
        r1[i] = *reinterpret_cast<const float4*>(iT1 + idx);
        rC[i] = *reinterpret_cast<const float4*>(iC  + idx);
    }
    float av = (tid < 128) ? a[tid] : 0.0f;
#pragma unroll
    for (int i = 0; i < 4; ++i) {
        int idx = tid * 4 + i * 1024;
        int u = idx >> 6, c = idx & 63;
        int base = u * TS + c;
        st4(S.Ws + base, rW[i]);
        st4(S.X0 + base, r0[i]);
        st4(S.X1 + base, r1[i]);
        st4(S.XC + base, rC[i]);
    }
    if (tid < 128) S.a_s[tid] = av;
    __syncthreads();

    // ---- stage 1: wa dots (t<128)  ||  first-branch colsums (t>=128) -------
    if (tid < 128) {
        int c = tid & 63;
        const float* a2 = S.a_s + ((tid >> 6) << 6);
        const float* wr = S.Ws + c * TS;
        float r0a = 0.f, r1a = 0.f, r2a = 0.f, r3a = 0.f;
#pragma unroll
        for (int o = 0; o < 64; o += 4) {
            r0a = fmaf(wr[o + 0], a2[o + 0], r0a);
            r1a = fmaf(wr[o + 1], a2[o + 1], r1a);
            r2a = fmaf(wr[o + 2], a2[o + 2], r2a);
            r3a = fmaf(wr[o + 3], a2[o + 3], r3a);
        }
        ((tid < 64) ? S.wa0 : S.wa1)[c] = (r0a + r1a) + (r2a + r3a);
    } else if (first) {
        // column sums of XC over w in [0,32) (lo) and [32,64) (hi)
        int t2 = tid - 128;
        int c = t2 & 63; bool hi = (t2 >= 64);
        const float* base = S.XC + (hi ? 32 * TS : 0) + c;
        float r0a = 0.f, r1a = 0.f, r2a = 0.f, r3a = 0.f;
#pragma unroll
        for (int w = 0; w < 32; w += 4) {
            r0a += base[(w + 0) * TS]; r1a += base[(w + 1) * TS];
            r2a += base[(w + 2) * TS]; r3a += base[(w + 3) * TS];
        }
        (hi ? S.v1 : S.v0)[c] = (r0a + r1a) + (r2a + r3a);
    }
    __syncthreads();

    // ---- stage 2: p/q — 256 threads, one dot each ---------------------------
    {
        int u = tid & 63, sel = tid >> 6;
        const float* row = ((sel & 2) ? S.X1 : S.X0) + u * TS;
        const float* wv  = (sel & 1) ? S.wa1 : S.wa0;
        float r0a = 0.f, r1a = 0.f, r2a = 0.f, r3a = 0.f;
#pragma unroll
        for (int c = 0; c < 64; c += 4) {
            r0a = fmaf(row[c + 0], wv[c + 0], r0a);
            r1a = fmaf(row[c + 1], wv[c + 1], r1a);
            r2a = fmaf(row[c + 2], wv[c + 2], r2a);
            r3a = fmaf(row[c + 3], wv[c + 3], r3a);
        }
        float r = (r0a + r1a) + (r2a + r3a);
        float* dst = (sel == 0) ? S.p0 : (sel == 1) ? S.q0 : (sel == 2) ? S.p1 : S.q1;
        dst[u] = r;
    }
    __syncthreads();

    const size_t obase = (size_t)b * 4096;

    if (first) {
        // closed-form softmax (t<64)  ||  Sv = v @ W (t in [64,192))
        if (tid < 64) {
            int v = tid;
            const float* pp = (v < 32) ? S.p0 : S.p1;
            const float* qq = (v < 32) ? S.q0 : S.q1;
            int i0 = (2 * v) & 63, i1 = (2 * v + 1) & 63;
            float eL = lrelu(pp[i0] + qq[i0]);
            float eH = lrelu(pp[i1] + qq[i1]);
            float m  = fmaxf(eL, eH);
            float wl = expf(eL - m), wh = expf(eH - m);
            float den = 32.0f * (wl + wh);
            S.s0[v] = wl / den;
            S.s1[v] = wh / den;
        } else if (tid < 192) {
            int t2 = tid - 64;
            int o = t2 & 63; bool hi = (t2 >= 64);
            const float* vv = hi ? S.v1 : S.v0;
            float r0a = 0.f, r1a = 0.f, r2a = 0.f, r3a = 0.f;
#pragma unroll
            for (int c = 0; c < 64; c += 4) {
                r0a = fmaf(vv[c + 0], S.Ws[(c + 0) * TS + o], r0a);
                r1a = fmaf(vv[c + 1], S.Ws[(c + 1) * TS + o], r1a);
                r2a = fmaf(vv[c + 2], S.Ws[(c + 2) * TS + o], r2a);
                r3a = fmaf(vv[c + 3], S.Ws[(c + 3) * TS + o], r3a);
            }
            (hi ? S.h1 : S.h0)[o] = (r0a + r1a) + (r2a + r3a);
        }
        __syncthreads();
        // h_prime[v][o] = aL[v]*S_L[o] + aH[v]*S_H[o], elu; attn[v][w]
#pragma unroll
        for (int r = 0; r < 4; ++r) {
            int idx = r * 1024 + tid * 4;
            int v = idx >> 6, o = idx & 63;
            float aL = S.s0[v], aH = S.s1[v];
            float4 oh;
            oh.x = elu1(fmaf(aL, S.h0[o + 0], aH * S.h1[o + 0]));
            oh.y = elu1(fmaf(aL, S.h0[o + 1], aH * S.h1[o + 1]));
            oh.z = elu1(fmaf(aL, S.h0[o + 2], aH * S.h1[o + 2]));
            oh.w = elu1(fmaf(aL, S.h0[o + 3], aH * S.h1[o + 3]));
            *reinterpret_cast<float4*>(out_h + obase + idx) = oh;
            float avv = (o < 32) ? aL : aH;
            float4 oa; oa.x = avv; oa.y = avv; oa.z = avv; oa.w = avv;
            *reinterpret_cast<float4*>(out_att + obase + idx) = oa;
        }
    } else {
        // fused e + softmax: warp 0 -> row lo (v<32), warp 1 -> row hi
        if (warp < 2) {
            const float* pp = warp ? S.p1 : S.p0;
            const float* qq = warp ? S.q1 : S.q0;
            int wlo = lane, whi = lane + 32;
            float e0 = lrelu(pp[(2 * wlo) & 63] + qq[(2 * wlo + 1) & 63]);
            float e1 = lrelu(pp[(2 * whi) & 63] + qq[(2 * whi + 1) & 63]);
            float m  = wmax(fmaxf(e0, e1));
            float x0 = expf(e0 - m), x1 = expf(e1 - m);
            float den = wsum(x0 + x1);
            float* s = warp ? S.s1 : S.s0;
            s[lane]      = x0 / den;
            s[lane + 32] = x1 / den;
        }
        __syncthreads();
        // u[c] = attn_row @ XC[:, c]
        if (tid < 128) {
            int c = tid & 63; bool hi = (tid >= 64);
            const float* att = hi ? S.s1 : S.s0;
            const float* col = S.XC + c;
            float r0a = 0.f, r1a = 0.f, r2a = 0.f, r3a = 0.f;
#pragma unroll
            for (int w = 0; w < 64; w += 4) {
                r0a = fmaf(att[w + 0], col[(w + 0) * TS], r0a);
                r1a = fmaf(att[w + 1], col[(w + 1) * TS], r1a);
                r2a = fmaf(att[w + 2], col[(w + 2) * TS], r2a);
                r3a = fmaf(att[w + 3], col[(w + 3) * TS], r3a);
            }
            (hi ? S.v1 : S.v0)[c] = (r0a + r1a) + (r2a + r3a);
        }
        __syncthreads();
        // hp[o] = u @ W, elu
        if (tid < 128) {
            int o = tid & 63; bool hi = (tid >= 64);
            const float* vv = hi ? S.v1 : S.v0;
            float r0a = 0.f, r1a = 0.f, r2a = 0.f, r3a = 0.f;
#pragma unroll
            for (int c = 0; c < 64; c += 4) {
                r0a = fmaf(vv[c + 0], S.Ws[(c + 0) * TS + o], r0a);
                r1a = fmaf(vv[c + 1], S.Ws[(c + 1) * TS + o], r1a);
                r2a = fmaf(vv[c + 2], S.Ws[(c + 2) * TS + o], r2a);
                r3a = fmaf(vv[c + 3], S.Ws[(c + 3) * TS + o], r3a);
            }
            (hi ? S.h1 : S.h0)[o] = elu1((r0a + r1a) + (r2a + r3a));
        }
        __syncthreads();
#pragma unroll
        for (int r = 0; r < 4; ++r) {
            int idx = r * 1024 + tid * 4;
            int v = idx >> 6, o = idx & 63;
            const float* hr = (v < 32) ? S.h0 : S.h1;
            const float* ar = (v < 32) ? S.s0 : S.s1;
            float4 oh; oh.x = hr[o]; oh.y = hr[o + 1]; oh.z = hr[o + 2]; oh.w = hr[o + 3];
            *reinterpret_cast<float4*>(out_h + obase + idx) = oh;
            float4 oa; oa.x = ar[o]; oa.y = ar[o + 1]; oa.z = ar[o + 2]; oa.w = ar[o + 3];
            *reinterpret_cast<float4*>(out_att + obase + idx) = oa;
        }
    }
}

extern "C" void kernel_launch(void* const* d_in, const int* in_sizes, int n_in,
                              void* d_out, int out_size) {
    const float* inp = (const float*)d_in[0];   // [16,12,64,64]
    // d_in[1] = adj : dead code in the reference
    const float* W   = (const float*)d_in[2];   // [64,64]
    const float* a   = (const float*)d_in[3];   // [128,1]
    float* out = (float*)d_out;                 // elu(h_prime) then attention
    int nt = in_sizes[0] / 4096;                // n*t = 192
    static int smem_set = 0;
    int smem = (int)sizeof(Smem);
    if (!smem_set) {
        cudaFuncSetAttribute(gat_kernel, cudaFuncAttributeMaxDynamicSharedMemorySize, smem);
        smem_set = 1;
    }
    gat_kernel<<<nt, 256, smem>>>(inp, W, a, out, out + out_size / 2);
}

// round 4
// speedup vs baseline: 1.0208x; 1.0208x over previous
#include <cuda_runtime.h>

// GAT layer, shapes fixed: n=16, t=12, N=64, c=o=64. adj is dead code.
// Degenerate tile/cat(dim=1)/view algebra (verified R1-R3, rel_err 4e-7):
//   wa0 = W @ a[:64], wa1 = W @ a[64:]
//   p[T,u] = inp[n,T,u,:]·wa0,  q[T,u] = inp[n,T,u,:]·wa1
//   tt<6 : e[v,w] = lrelu( (p+q)[2tt+(v>=32), (2v+(w>=32))%64] )  -> 2 distinct
//          values per softmax row -> closed-form softmax.
//   tt>=6: e[v,w] = lrelu( p[2(tt-6)+(v>=32),(2w)%64] + q[...,(2w+1)%64] )
//          -> 2 distinct attention rows.
//   h_prime = (attn @ inp[n,tt]) @ W; elu.
// R4: 96 blocks (ONE wave on 148 SMs), 2 independent units per block on
// disjoint 128-thread halves with named barriers; W staged once per block.

#define NT 12
#define LRELU_A 0.2f
#define TS 65

struct Unit {
    float X0[64 * TS], X1[64 * TS], XC[64 * TS];   // X[u*TS+c] = inp[T][u][c]
    float wa0[64], wa1[64];
    float p0[64], q0[64], p1[64], q1[64];
    float s0[64], s1[64];
    float v0[64], v1[64];
    float h0[64], h1[64];
};
struct Smem {
    float Ws[64 * TS];    // Ws[c*TS+o] = W[c][o]
    float a_s[128];
    Unit un[2];
};

__device__ __forceinline__ float wsum(float v) {
#pragma unroll
    for (int s = 16; s; s >>= 1) v += __shfl_xor_sync(0xffffffffu, v, s);
    return v;
}
__device__ __forceinline__ float wmax(float v) {
#pragma unroll
    for (int s = 16; s; s >>= 1) v = fmaxf(v, __shfl_xor_sync(0xffffffffu, v, s));
    return v;
}
__device__ __forceinline__ float elu1(float x)  { return x > 0.0f ? x : expm1f(x); }
__device__ __forceinline__ float lrelu(float x) { return x > 0.0f ? x : LRELU_A * x; }
__device__ __forceinline__ void st4(float* b, float4 v) {
    b[0] = v.x; b[1] = v.y; b[2] = v.z; b[3] = v.w;
}

__global__ void __launch_bounds__(256) gat_kernel(
    const float* __restrict__ inp, const float* __restrict__ W,
    const float* __restrict__ a, float* __restrict__ out_h,
    float* __restrict__ out_att)
{
    extern __shared__ Smem S[];
    const int tid  = threadIdx.x;
    const int half = tid >> 7;            // warp-uniform
    const int ut   = tid & 127;
    const int b    = blockIdx.x * 2 + half;     // (nn,tt) unit
    const int tt   = b % NT;
    const int nn   = b / NT;
    Unit& U = S->un[half];
    const int bar = half + 1;

#define HBAR() asm volatile("bar.sync %0, 128;" :: "r"(bar) : "memory")

    const bool first = (tt < 6);
    const int  T0    = first ? 2 * tt : 2 * (tt - 6);
    const float* __restrict__ iT0 = inp + ((size_t)nn * NT + T0) * 4096;
    const float* __restrict__ iT1 = iT0 + 4096;
    const float* __restrict__ iC  = inp + ((size_t)nn * NT + tt) * 4096;

    // ---- loads: W by all 256 threads; X tiles per half; a by tid<128 ------
#pragma unroll
    for (int i = 0; i < 4; ++i) {
        int idx = tid * 4 + i * 1024;
        float4 w = *reinterpret_cast<const float4*>(W + idx);
        st4(S->Ws + (idx >> 6) * TS + (idx & 63), w);
    }
    if (tid < 128) S->a_s[tid] = a[tid];
#pragma unroll
    for (int i = 0; i < 8; ++i) {
        int idx = ut * 4 + i * 512;
        float4 v0 = *reinterpret_cast<const float4*>(iT0 + idx);
        float4 v1 = *reinterpret_cast<const float4*>(iT1 + idx);
        float4 vc = *reinterpret_cast<const float4*>(iC  + idx);
        int base = (idx >> 6) * TS + (idx & 63);
        st4(U.X0 + base, v0);
        st4(U.X1 + base, v1);
        st4(U.XC + base, vc);
    }
    __syncthreads();   // once: both halves + shared Ws/a ready

    // ---- stage A: wa dot (all 128) ; colsums (first branch, fused) --------
    {
        int c = ut & 63;
        const float* a2 = S->a_s + ((ut >> 6) << 6);
        const float* wr = S->Ws + c * TS;
        float r0 = 0.f, r1 = 0.f, r2 = 0.f, r3 = 0.f;
#pragma unroll
        for (int o = 0; o < 64; o += 4) {
            r0 = fmaf(wr[o + 0], a2[o + 0], r0);
            r1 = fmaf(wr[o + 1], a2[o + 1], r1);
            r2 = fmaf(wr[o + 2], a2[o + 2], r2);
            r3 = fmaf(wr[o + 3], a2[o + 3], r3);
        }
        ((ut < 64) ? U.wa0 : U.wa1)[c] = (r0 + r1) + (r2 + r3);
        if (first) {
            bool hi = (ut >= 64);
            const float* base = U.XC + (hi ? 32 * TS : 0) + c;
            float s0a = 0.f, s1a = 0.f, s2a = 0.f, s3a = 0.f;
#pragma unroll
            for (int w = 0; w < 32; w += 4) {
                s0a += base[(w + 0) * TS]; s1a += base[(w + 1) * TS];
                s2a += base[(w + 2) * TS]; s3a += base[(w + 3) * TS];
            }
            (hi ? U.v1 : U.v0)[c] = (s0a + s1a) + (s2a + s3a);
        }
    }
    HBAR();

    // ---- stage B: p/q for both slices per thread ; Sv gemv (first) --------
    {
        int u = ut & 63;
        const float* row0 = U.X0 + u * TS;
        const float* row1 = U.X1 + u * TS;
        const float* wv   = (ut < 64) ? U.wa0 : U.wa1;
        float a0 = 0.f, a1 = 0.f, b0 = 0.f, b1 = 0.f;
#pragma unroll
        for (int c = 0; c < 64; c += 2) {
            float w0 = wv[c], w1 = wv[c + 1];
            a0 = fmaf(row0[c], w0, a0); a1 = fmaf(row0[c + 1], w1, a1);
            b0 = fmaf(row1[c], w0, b0); b1 = fmaf(row1[c + 1], w1, b1);
        }
        if (ut < 64) { U.p0[u] = a0 + a1; U.p1[u] = b0 + b1; }
        else         { U.q0[u] = a0 + a1; U.q1[u] = b0 + b1; }
        if (first) {
            int o = ut & 63; bool hi = (ut >= 64);
            const float* vv = hi ? U.v1 : U.v0;
            float r0 = 0.f, r1 = 0.f, r2 = 0.f, r3 = 0.f;
#pragma unroll
            for (int c = 0; c < 64; c += 4) {
                r0 = fmaf(vv[c + 0], S->Ws[(c + 0) * TS + o], r0);
                r1 = fmaf(vv[c + 1], S->Ws[(c + 1) * TS + o], r1);
                r2 = fmaf(vv[c + 2], S->Ws[(c + 2) * TS + o], r2);
                r3 = fmaf(vv[c + 3], S->Ws[(c + 3) * TS + o], r3);
            }
            (hi ? U.h1 : U.h0)[o] = (r0 + r1) + (r2 + r3);
        }
    }
    HBAR();

    const size_t obase = (size_t)b * 4096;

    if (first) {
        // closed-form softmax: two values per row
        if (ut < 64) {
            int v = ut;
            const float* pp = (v < 32) ? U.p0 : U.p1;
            const float* qq = (v < 32) ? U.q0 : U.q1;
            int i0 = (2 * v) & 63, i1 = (2 * v + 1) & 63;
            float eL = lrelu(pp[i0] + qq[i0]);
            float eH = lrelu(pp[i1] + qq[i1]);
            float m  = fmaxf(eL, eH);
            float wl = expf(eL - m), wh = expf(eH - m);
            float den = 32.0f * (wl + wh);
            U.s0[v] = wl / den;
            U.s1[v] = wh / den;
        }
        HBAR();
#pragma unroll
        for (int r = 0; r < 8; ++r) {
            int idx = r * 512 + ut * 4;
            int v = idx >> 6, o = idx & 63;
            float aL = U.s0[v], aH = U.s1[v];
            float4 oh;
            oh.x = elu1(fmaf(aL, U.h0[o + 0], aH * U.h1[o + 0]));
            oh.y = elu1(fmaf(aL, U.h0[o + 1], aH * U.h1[o + 1]));
            oh.z = elu1(fmaf(aL, U.h0[o + 2], aH * U.h1[o + 2]));
            oh.w = elu1(fmaf(aL, U.h0[o + 3], aH * U.h1[o + 3]));
            *reinterpret_cast<float4*>(out_h + obase + idx) = oh;
            float av = (o < 32) ? aL : aH;
            float4 oa; oa.x = av; oa.y = av; oa.z = av; oa.w = av;
            *reinterpret_cast<float4*>(out_att + obase + idx) = oa;
        }
    } else {
        // fused e + softmax: 2 warps (row lo / row hi)
        if (ut < 64) {
            const float* pp = (ut >= 32) ? U.p1 : U.p0;
            const float* qq = (ut >= 32) ? U.q1 : U.q0;
            int lane = ut & 31;
            float e0 = lrelu(pp[(2 * lane) & 63]      + qq[(2 * lane + 1) & 63]);
            float e1 = lrelu(pp[(2 * (lane + 32)) & 63] + qq[(2 * (lane + 32) + 1) & 63]);
            float m  = wmax(fmaxf(e0, e1));
            float x0 = expf(e0 - m), x1 = expf(e1 - m);
            float den = wsum(x0 + x1);
            float* s = (ut >= 32) ? U.s1 : U.s0;
            s[lane]      = x0 / den;
            s[lane + 32] = x1 / den;
        }
        HBAR();
        // u[c] = attn_row @ XC[:, c]
        {
            int c = ut & 63; bool hi = (ut >= 64);
            const float* att = hi ? U.s1 : U.s0;
            const float* col = U.XC + c;
            float r0 = 0.f, r1 = 0.f, r2 = 0.f, r3 = 0.f;
#pragma unroll
            for (int w = 0; w < 64; w += 4) {
                r0 = fmaf(att[w + 0], col[(w + 0) * TS], r0);
                r1 = fmaf(att[w + 1], col[(w + 1) * TS], r1);
                r2 = fmaf(att[w + 2], col[(w + 2) * TS], r2);
                r3 = fmaf(att[w + 3], col[(w + 3) * TS], r3);
            }
            (hi ? U.v1 : U.v0)[c] = (r0 + r1) + (r2 + r3);
        }
        HBAR();
        // hp[o] = u @ W, elu
        {
            int o = ut & 63; bool hi = (ut >= 64);
            const float* vv = hi ? U.v1 : U.v0;
            float r0 = 0.f, r1 = 0.f, r2 = 0.f, r3 = 0.f;
#pragma unroll
            for (int c = 0; c < 64; c += 4) {
                r0 = fmaf(vv[c + 0], S->Ws[(c + 0) * TS + o], r0);
                r1 = fmaf(vv[c + 1], S->Ws[(c + 1) * TS + o], r1);
                r2 = fmaf(vv[c + 2], S->Ws[(c + 2) * TS + o], r2);
                r3 = fmaf(vv[c + 3], S->Ws[(c + 3) * TS + o], r3);
            }
            (hi ? U.h1 : U.h0)[o] = elu1((r0 + r1) + (r2 + r3));
        }
        HBAR();
#pragma unroll
        for (int r = 0; r < 8; ++r) {
            int idx = r * 512 + ut * 4;
            int v = idx >> 6, o = idx & 63;
            const float* hr = (v < 32) ? U.h0 : U.h1;
            const float* ar = (v < 32) ? U.s0 : U.s1;
            float4 oh; oh.x = hr[o]; oh.y = hr[o + 1]; oh.z = hr[o + 2]; oh.w = hr[o + 3];
            *reinterpret_cast<float4*>(out_h + obase + idx) = oh;
            float4 oa; oa.x = ar[o]; oa.y = ar[o + 1]; oa.z = ar[o + 2]; oa.w = ar[o + 3];
            *reinterpret_cast<float4*>(out_att + obase + idx) = oa;
        }
    }
#undef HBAR
}

extern "C" void kernel_launch(void* const* d_in, const int* in_sizes, int n_in,
                              void* d_out, int out_size) {
    const float* inp = (const float*)d_in[0];   // [16,12,64,64]
    // d_in[1] = adj : dead code in the reference
    const float* W   = (const float*)d_in[2];   // [64,64]
    const float* a   = (const float*)d_in[3];   // [128,1]
    float* out = (float*)d_out;                 // elu(h_prime) then attention
    int nt = in_sizes[0] / 4096;                // n*t = 192
    int smem = (int)sizeof(Smem);
    static int smem_set = 0;
    if (!smem_set) {
        cudaFuncSetAttribute(gat_kernel, cudaFuncAttributeMaxDynamicSharedMemorySize, smem);
        smem_set = 1;
    }
    gat_kernel<<<nt / 2, 256, smem>>>(inp, W, a, out, out + out_size / 2);
}